// round 16
// baseline (speedup 1.0000x reference)
#include <cuda_runtime.h>

// GraphVampNet EGNN, sm_103a. Round 16: QUAD-split (4 lanes/node, 4 outputs
// per lane) at <=64 regs so 2 CTAs x 512 threads = 32 warps/SM (2x latency
// hiding vs the 16-warp pair-split plateau). Keeps: f32x2 packing, 2-edge
// weight sharing, 4-group XOR partner GEMVs, tanh silu, deferred coord
// reduction, smem-exchange Phase C, parallel pooling.
// B=512 frames, N=128 nodes, K=16 neighbors (j=(i+d)&127), H=16, NL=4, NC=6.

#define B_  512
#define N_  128
#define K_  16
#define H_  16
#define NC_ 6
#define NL_ 4

#define SZ_E1 (34*16)
#define SZ_E2 (16*16)
#define SZ_N1 (32*16)
#define SZ_N2 (16*16)
#define SZ_C1 (16*16)
#define SZ_C2 (16)

// pad CTA smem above 228/3 KB so at most 2 CTAs resident (belt+braces; the
// 64-reg x 512-thread budget already caps at 2).
#define SMEM_PAD 9000

#define FULL 0xffffffffu
#define HS 20   // node-state row stride (words)

typedef unsigned long long u64;

// silu(v) = t + t*tanh(t), t = v/2  (1 MUFU; abs err ~1e-4-class << 1e-3 tol)
__device__ __forceinline__ float silu_f(float v) {
    const float t = 0.5f * v;
    float th;
    asm("tanh.approx.f32 %0, %1;" : "=f"(th) : "f"(t));
    return fmaf(t, th, t);
}
__device__ __forceinline__ float4 ld4(const float* p) {
    return *reinterpret_cast<const float4*>(p);
}
__device__ __forceinline__ ulonglong2 ldu2(const float* p) {
    return *reinterpret_cast<const ulonglong2*>(p);
}
__device__ __forceinline__ u64 bc2(float s) {
    u64 r; asm("mov.b64 %0, {%1, %1};" : "=l"(r) : "f"(s)); return r;
}
__device__ __forceinline__ void up2(u64 v, float &x, float &y) {
    asm("mov.b64 {%0, %1}, %2;" : "=f"(x), "=f"(y) : "l"(v));
}
__device__ __forceinline__ void ffma2(u64 &acc, u64 w, u64 s) {
    asm("fma.rn.f32x2 %0, %1, %2, %0;" : "+l"(acc) : "l"(w), "l"(s));
}
__device__ __forceinline__ void fadd2(u64 &acc, u64 a) {
    asm("add.rn.f32x2 %0, %1, %0;" : "+l"(acc) : "l"(a));
}
// acc (2 u64 = 4 outs) += s2 * w[0..3]   (1x LDS.128 + 2 FFMA2)
__device__ __forceinline__ void pfma4(u64 (&A)[2], u64 s2, const float* w) {
    ulonglong2 w0 = ldu2(w);
    ffma2(A[0], w0.x, s2); ffma2(A[1], w0.y, s2);
}
__device__ __forceinline__ void pbias4(u64 (&A)[2], const float* p) {
    ulonglong2 b0 = ldu2(p);
    A[0] = b0.x; A[1] = b0.y;
}
__device__ __forceinline__ void unp4(const u64 (&A)[2], float (&o)[4]) {
    up2(A[0], o[0], o[1]); up2(A[1], o[2], o[3]);
}
__device__ __forceinline__ void load16(float (&r)[16], const float* p) {
    float4 v0 = ld4(p), v1 = ld4(p+4), v2 = ld4(p+8), v3 = ld4(p+12);
    r[0]=v0.x; r[1]=v0.y; r[2]=v0.z; r[3]=v0.w;
    r[4]=v1.x; r[5]=v1.y; r[6]=v1.z; r[7]=v1.w;
    r[8]=v2.x; r[9]=v2.y; r[10]=v2.z; r[11]=v2.w;
    r[12]=v3.x; r[13]=v3.y; r[14]=v3.z; r[15]=v3.w;
}
__device__ __forceinline__ void st4f(float* p, const float (&a)[4]) {
    *reinterpret_cast<float4*>(p) = make_float4(a[0], a[1], a[2], a[3]);
}
__device__ __forceinline__ void stu1(float* p, const u64 (&A)[2]) {
    ulonglong2 v; v.x = A[0]; v.y = A[1];
    *reinterpret_cast<ulonglong2*>(p) = v;
}
// e1 for one edge, quad slice: o = silu(pre + y_j + rad*w32) (own 4 cols)
__device__ __forceinline__ void e1q(float (&o)[4], const float* yrow,
                                    const u64 (&pre)[2], ulonglong2 w32,
                                    float rad) {
    ulonglong2 ya = ldu2(yrow);
    u64 A[2] = {ya.x, ya.y};
    fadd2(A[0], pre[0]); fadd2(A[1], pre[1]);
    const u64 r2 = bc2(rad);
    ffma2(A[0], w32.x, r2); ffma2(A[1], w32.y, r2);
    unp4(A, o);
    #pragma unroll
    for (int k = 0; k < 4; ++k) o[k] = silu_f(o[k]);
}

__global__ void __launch_bounds__(4 * N_, 2)
egnn_kernel(const float* __restrict__ data,      // [B, N, 3+N]
            const float* __restrict__ emb_w,     // [N, H]
            const float* __restrict__ ein_w, const float* __restrict__ ein_b,
            const float* __restrict__ eout_w, const float* __restrict__ eout_b,
            const float* __restrict__ fc_w,  const float* __restrict__ fc_b,
            const float* __restrict__ e1_w,  const float* __restrict__ e1_b,
            const float* __restrict__ e2_w,  const float* __restrict__ e2_b,
            const float* __restrict__ n1_w,  const float* __restrict__ n1_b,
            const float* __restrict__ n2_w,  const float* __restrict__ n2_b,
            const float* __restrict__ c1_w,  const float* __restrict__ c1_b,
            const float* __restrict__ c2_w,
            float* __restrict__ out)             // [B, NC]
{
    const int b   = blockIdx.x;
    const int tid = threadIdx.x;
    const int i   = tid >> 2;        // node 0..127
    const int q   = tid & 3;         // lane within quad
    const int q4  = q * 4;           // owned output-column slice base

    __shared__ __align__(16) float s_h[N_][HS];     // quad-private features
    __shared__ __align__(16) float s_y[N_][HS];     // e1 neighbor-half
    __shared__ __align__(16) float s_acc[N_][HS];   // accm / na exchange
    __shared__ __align__(16) float4 s_x4[N_];
    __shared__ __align__(16) float s_part[32][17];  // pooling partials

    __shared__ __align__(16) float w_e1[NL_ * SZ_E1 + SMEM_PAD], w_e2[NL_ * SZ_E2];
    __shared__ __align__(16) float w_n1[NL_ * SZ_N1], w_n2[NL_ * SZ_N2];
    __shared__ __align__(16) float w_c1[NL_ * SZ_C1], w_c2[NL_ * SZ_C2];
    __shared__ __align__(16) float b_e1[NL_ * 16], b_e2[NL_ * 16];
    __shared__ __align__(16) float b_n1[NL_ * 16], b_n2[NL_ * 16], b_c1[NL_ * 16];
    __shared__ __align__(16) float s_ein[16 * 16], sb_ein[16];
    __shared__ __align__(16) float s_eout[16 * 16], sb_eout[16];
    __shared__ float s_fc[16 * NC_], sb_fc[NC_];
    __shared__ float s_pool[H_];

    const int NT = 4 * N_;
    for (int t = tid; t < NL_ * SZ_E1; t += NT) w_e1[t] = e1_w[t];
    for (int t = tid; t < NL_ * SZ_E2; t += NT) w_e2[t] = e2_w[t];
    for (int t = tid; t < NL_ * SZ_N1; t += NT) w_n1[t] = n1_w[t];
    for (int t = tid; t < NL_ * SZ_N2; t += NT) w_n2[t] = n2_w[t];
    for (int t = tid; t < NL_ * SZ_C1; t += NT) w_c1[t] = c1_w[t];
    for (int t = tid; t < NL_ * SZ_C2; t += NT) w_c2[t] = c2_w[t];
    for (int t = tid; t < NL_ * 16; t += NT) {
        b_e1[t] = e1_b[t]; b_e2[t] = e2_b[t];
        b_n1[t] = n1_b[t]; b_n2[t] = n2_b[t]; b_c1[t] = c1_b[t];
    }
    for (int t = tid; t < 16 * 16; t += NT) { s_ein[t] = ein_w[t]; s_eout[t] = eout_w[t]; }
    if (tid < 16) { sb_ein[tid] = ein_b[tid]; sb_eout[tid] = eout_b[tid]; }
    for (int t = tid; t < 16 * NC_; t += NT) s_fc[t] = fc_w[t];
    if (tid < NC_) sb_fc[tid] = fc_b[tid];

    float xi0, xi1, xi2;
    {
        const float* dptr = data + ((size_t)b * N_ + i) * (3 + N_);
        xi0 = dptr[0]; xi1 = dptr[1]; xi2 = dptr[2];
    }
    __syncthreads();

    // ---- init: h = emb @ ein_w + ein_b  (quad splits 16 outputs 4x4) ----
    {
        u64 acc[2];
        pbias4(acc, sb_ein + q4);
        const float* er = emb_w + i * H_;
        #pragma unroll
        for (int k = 0; k < 16; ++k) pfma4(acc, bc2(er[k]), s_ein + k * 16 + q4);
        stu1(&s_h[i][q4], acc);
        if (q == 0) s_x4[i] = make_float4(xi0, xi1, xi2, 0.0f);
    }
    __syncthreads();

    // ---- E_GCL layers ----
    #pragma unroll 1
    for (int l = 0; l < NL_; ++l) {
        const float* We1q = w_e1 + l * SZ_E1 + q4;   // col-sliced e1
        const float* E2b  = w_e2 + l * SZ_E2;
        const float* C1b  = w_c1 + l * SZ_C1;

        // Phase A: pre = bias + e_attr row + h_i @ rows0-15 (own 4 cols);
        //          y_i = h_i @ rows16-31 -> s_y
        u64 pre[2];
        {
            float hf[16]; load16(hf, &s_h[i][0]);
            pbias4(pre, b_e1 + l * 16 + q4);
            pfma4(pre, bc2(1.0f), We1q + 33 * 16);
            u64 yq[2] = {0, 0};
            #pragma unroll
            for (int k = 0; k < 16; ++k) {
                const u64 s2 = bc2(hf[k]);
                pfma4(pre, s2, We1q + k * 16);
                pfma4(yq,  s2, We1q + (16 + k) * 16);
            }
            stu1(&s_y[i][q4], yq);
        }
        __syncthreads();   // s_y + s_x visible block-wide

        const ulonglong2 w32 = ldu2(We1q + 32 * 16);   // hoisted (4 regs)

        float accm[4] = {0.f, 0.f, 0.f, 0.f};
        float ax0 = 0.f, ax1 = 0.f, ax2 = 0.f;   // partial-t accumulators

        #pragma unroll 1
        for (int it = 0; it < 8; ++it) {       // 2 edges per iteration
            const int d  = 1 + 2 * it;
            const int j0 = (i + d)     & (N_ - 1);
            const int j1 = (i + d + 1) & (N_ - 1);
            float4 xj0 = s_x4[j0];
            float4 xj1 = s_x4[j1];
            const float d00 = xi0-xj0.x, d01 = xi1-xj0.y, d02 = xi2-xj0.z;
            const float d10 = xi0-xj1.x, d11 = xi1-xj1.y, d12 = xi2-xj1.z;
            const float rad0 = fmaf(d00,d00, fmaf(d01,d01, d02*d02));
            const float rad1 = fmaf(d10,d10, fmaf(d11,d11, d12*d12));

            // e1 (own 4 cols)
            float a0[4], a1[4];
            e1q(a0, &s_y[j0][q4], pre, w32, rad0);
            e1q(a1, &s_y[j1][q4], pre, w32, rad1);

            // e2: m = silu(a_full @ We2 + b); 4 XOR groups over the quad
            float m0[4], m1[4];
            {
                u64 M0[2], M1[2];
                pbias4(M0, b_e2 + l * 16 + q4);
                M1[0] = M0[0]; M1[1] = M0[1];
                {   // g = 0: own rows, scalars from registers
                    const float* W = E2b + (q4 << 4) + q4;
                    #pragma unroll
                    for (int rr = 0; rr < 4; ++rr) {
                        ulonglong2 w = ldu2(W + rr * 16);
                        const u64 s0 = bc2(a0[rr]), s1 = bc2(a1[rr]);
                        ffma2(M0[0], w.x, s0); ffma2(M0[1], w.y, s0);
                        ffma2(M1[0], w.x, s1); ffma2(M1[1], w.y, s1);
                    }
                }
                #pragma unroll
                for (int g = 1; g < 4; ++g) {
                    const float* W = E2b + (((q ^ g) * 4) << 4) + q4;
                    #pragma unroll
                    for (int rr = 0; rr < 4; ++rr) {
                        ulonglong2 w = ldu2(W + rr * 16);
                        const u64 s0 = bc2(__shfl_xor_sync(FULL, a0[rr], g, 4));
                        const u64 s1 = bc2(__shfl_xor_sync(FULL, a1[rr], g, 4));
                        ffma2(M0[0], w.x, s0); ffma2(M0[1], w.y, s0);
                        ffma2(M1[0], w.x, s1); ffma2(M1[1], w.y, s1);
                    }
                }
                unp4(M0, m0); unp4(M1, m1);
            }
            #pragma unroll
            for (int o = 0; o < 4; ++o) {
                m0[o] = silu_f(m0[o]); m1[o] = silu_f(m1[o]);
                accm[o] += m0[o] + m1[o];
            }

            // coord_mlp: t = silu(m_full @ Wc1 + b) . Wc2 (own-4 partial t)
            {
                u64 T0[2], T1[2];
                pbias4(T0, b_c1 + l * 16 + q4);
                T1[0] = T0[0]; T1[1] = T0[1];
                {
                    const float* W = C1b + (q4 << 4) + q4;
                    #pragma unroll
                    for (int rr = 0; rr < 4; ++rr) {
                        ulonglong2 w = ldu2(W + rr * 16);
                        const u64 s0 = bc2(m0[rr]), s1 = bc2(m1[rr]);
                        ffma2(T0[0], w.x, s0); ffma2(T0[1], w.y, s0);
                        ffma2(T1[0], w.x, s1); ffma2(T1[1], w.y, s1);
                    }
                }
                #pragma unroll
                for (int g = 1; g < 4; ++g) {
                    const float* W = C1b + (((q ^ g) * 4) << 4) + q4;
                    #pragma unroll
                    for (int rr = 0; rr < 4; ++rr) {
                        ulonglong2 w = ldu2(W + rr * 16);
                        const u64 s0 = bc2(__shfl_xor_sync(FULL, m0[rr], g, 4));
                        const u64 s1 = bc2(__shfl_xor_sync(FULL, m1[rr], g, 4));
                        ffma2(T0[0], w.x, s0); ffma2(T0[1], w.y, s0);
                        ffma2(T1[0], w.x, s1); ffma2(T1[1], w.y, s1);
                    }
                }
                unp4(T0, a0); unp4(T1, a1);   // reuse a regs
            }
            float t0, t1;
            {
                float4 w = ld4(w_c2 + l * SZ_C2 + q4);
                t0 = silu_f(a0[0]) * w.x;
                t0 = fmaf(silu_f(a0[1]), w.y, t0);
                t0 = fmaf(silu_f(a0[2]), w.z, t0);
                t0 = fmaf(silu_f(a0[3]), w.w, t0);
                t1 = silu_f(a1[0]) * w.x;
                t1 = fmaf(silu_f(a1[1]), w.y, t1);
                t1 = fmaf(silu_f(a1[2]), w.z, t1);
                t1 = fmaf(silu_f(a1[3]), w.w, t1);
            }
            // partial t (own 4 dims): full reduction deferred to layer end
            ax0 = fmaf(d00, t0, fmaf(d10, t1, ax0));
            ax1 = fmaf(d01, t0, fmaf(d11, t1, ax1));
            ax2 = fmaf(d02, t0, fmaf(d12, t1, ax2));
        }

        // single quad-reduction of partial coord accumulators
        ax0 += __shfl_xor_sync(FULL, ax0, 1, 4);
        ax0 += __shfl_xor_sync(FULL, ax0, 2, 4);
        ax1 += __shfl_xor_sync(FULL, ax1, 1, 4);
        ax1 += __shfl_xor_sync(FULL, ax1, 2, 4);
        ax2 += __shfl_xor_sync(FULL, ax2, 1, 4);
        ax2 += __shfl_xor_sync(FULL, ax2, 2, 4);
        xi0 = fmaf(ax0, 0.0625f, xi0);   // cnt == 16
        xi1 = fmaf(ax1, 0.0625f, xi1);
        xi2 = fmaf(ax2, 0.0625f, xi2);

        __syncthreads();   // all Phase-B reads of s_y / s_x done block-wide

        // Phase C: node_mlp (quad-split 4x4); exchanges via s_acc smem
        {
            const float* Wn1q = w_n1 + l * SZ_N1 + q4;
            const float* Wn2q = w_n2 + l * SZ_N2 + q4;

            st4f(&s_acc[i][q4], accm);
            __syncwarp();
            float hf[16]; load16(hf, &s_h[i][0]);
            float af[16]; load16(af, &s_acc[i][0]);   // full agg_m

            float na[4];
            {
                u64 NA[2];
                pbias4(NA, b_n1 + l * 16 + q4);
                #pragma unroll
                for (int k = 0; k < 16; ++k) {
                    pfma4(NA, bc2(hf[k]), Wn1q + k * 16);
                    pfma4(NA, bc2(af[k]), Wn1q + (16 + k) * 16);
                }
                unp4(NA, na);
            }
            #pragma unroll
            for (int o = 0; o < 4; ++o) na[o] = silu_f(na[o]);

            __syncwarp();                 // af reads done before overwrite
            st4f(&s_acc[i][q4], na);
            __syncwarp();
            float nf[16]; load16(nf, &s_acc[i][0]);

            float hb[4];
            {
                u64 HB[2];
                pbias4(HB, b_n2 + l * 16 + q4);
                #pragma unroll
                for (int k = 0; k < 16; ++k) pfma4(HB, bc2(nf[k]), Wn2q + k * 16);
                unp4(HB, hb);
            }
            {
                float4 r0 = ld4(&s_h[i][q4]);   // own residual slice
                hb[0] += r0.x; hb[1] += r0.y; hb[2] += r0.z; hb[3] += r0.w;
            }
            __syncwarp();          // quad's reads of old s_h row complete
            st4f(&s_h[i][q4], hb);
            if (q == 0) s_x4[i] = make_float4(xi0, xi1, xi2, 0.0f);
        }
        __syncwarp();
    }

    // ---- embedding_out + pooling ----
    {
        float hf[16]; load16(hf, &s_h[i][0]);
        u64 HO[2];
        pbias4(HO, sb_eout + q4);
        #pragma unroll
        for (int k = 0; k < 16; ++k) pfma4(HO, bc2(hf[k]), s_eout + k * 16 + q4);
        __syncwarp();    // quad reads of own row done before overwrite
        stu1(&s_h[i][q4], HO);
    }
    __syncthreads();

    // parallel pooling: thread (chunk = tid>>4, col = tid&15) sums 4 rows
    {
        const int col = tid & 15;
        const int chunk = tid >> 4;   // 0..31
        const int r0 = chunk * 4;
        float s = 0.0f;
        #pragma unroll
        for (int r = 0; r < 4; ++r) s += s_h[r0 + r][col];
        s_part[chunk][col] = s;
    }
    __syncthreads();
    if (tid < H_) {
        float s = 0.0f;
        #pragma unroll
        for (int c = 0; c < 32; ++c) s += s_part[c][tid];
        s_pool[tid] = s * (1.0f / (float)N_);
    }
    __syncthreads();

    if (tid == 0) {
        float logit[NC_];
        float mx = -1e30f;
        #pragma unroll
        for (int c = 0; c < NC_; ++c) {
            float s = sb_fc[c];
            #pragma unroll
            for (int k = 0; k < H_; ++k) s = fmaf(s_pool[k], s_fc[k * NC_ + c], s);
            logit[c] = s;
            mx = fmaxf(mx, s);
        }
        float den = 0.0f;
        float ev[NC_];
        #pragma unroll
        for (int c = 0; c < NC_; ++c) { ev[c] = expf(logit[c] - mx); den += ev[c]; }
        const float inv = 1.0f / den;
        #pragma unroll
        for (int c = 0; c < NC_; ++c) out[b * NC_ + c] = ev[c] * inv;
    }
}

extern "C" void kernel_launch(void* const* d_in, const int* in_sizes, int n_in,
                              void* d_out, int out_size)
{
    const float* data   = (const float*)d_in[0];
    const float* emb_w  = (const float*)d_in[3];
    const float* ein_w  = (const float*)d_in[4];
    const float* ein_b  = (const float*)d_in[5];
    const float* eout_w = (const float*)d_in[6];
    const float* eout_b = (const float*)d_in[7];
    const float* fc_w   = (const float*)d_in[8];
    const float* fc_b   = (const float*)d_in[9];
    const float* e1_w   = (const float*)d_in[10];
    const float* e1_b   = (const float*)d_in[11];
    const float* e2_w   = (const float*)d_in[12];
    const float* e2_b   = (const float*)d_in[13];
    const float* n1_w   = (const float*)d_in[14];
    const float* n1_b   = (const float*)d_in[15];
    const float* n2_w   = (const float*)d_in[16];
    const float* n2_b   = (const float*)d_in[17];
    const float* c1_w   = (const float*)d_in[18];
    const float* c1_b   = (const float*)d_in[19];
    const float* c2_w   = (const float*)d_in[20];
    float* out = (float*)d_out;

    egnn_kernel<<<B_, 4 * N_>>>(data, emb_w, ein_w, ein_b, eout_w, eout_b,
                                fc_w, fc_b, e1_w, e1_b, e2_w, e2_b,
                                n1_w, n1_b, n2_w, n2_b, c1_w, c1_b, c2_w, out);
}

// round 17
// speedup vs baseline: 1.2844x; 1.2844x over previous
#include <cuda_runtime.h>

// GraphVampNet EGNN, sm_103a. Round 17: quad-split (4 lanes/node) at 32
// warps/SM with pair-level MIO: 4-edge batching + smem-exchange of a/m
// vectors (zero partner SHFLs). f32x2 packing, tanh silu, deferred coord
// reduction, parallel pooling. <=64 regs x 512 thr x 2 CTA = full RF.
// B=512 frames, N=128 nodes, K=16 neighbors (j=(i+d)&127), H=16, NL=4, NC=6.

#define B_  512
#define N_  128
#define K_  16
#define H_  16
#define NC_ 6
#define NL_ 4

#define SZ_E1 (34*16)
#define SZ_E2 (16*16)
#define SZ_N1 (32*16)
#define SZ_N2 (16*16)
#define SZ_C1 (16*16)
#define SZ_C2 (16)

#define FULL 0xffffffffu
#define HS 20   // node-state row stride (words)
#define ES 68   // exchange row stride (words): 16B-aligned, bank-spread

typedef unsigned long long u64;

// silu(v) = t + t*tanh(t), t = v/2  (1 MUFU; abs err ~1e-4-class << 1e-3 tol)
__device__ __forceinline__ float silu_f(float v) {
    const float t = 0.5f * v;
    float th;
    asm("tanh.approx.f32 %0, %1;" : "=f"(th) : "f"(t));
    return fmaf(t, th, t);
}
__device__ __forceinline__ float4 ld4(const float* p) {
    return *reinterpret_cast<const float4*>(p);
}
__device__ __forceinline__ ulonglong2 ldu2(const float* p) {
    return *reinterpret_cast<const ulonglong2*>(p);
}
__device__ __forceinline__ u64 bc2(float s) {
    u64 r; asm("mov.b64 %0, {%1, %1};" : "=l"(r) : "f"(s)); return r;
}
__device__ __forceinline__ void up2(u64 v, float &x, float &y) {
    asm("mov.b64 {%0, %1}, %2;" : "=f"(x), "=f"(y) : "l"(v));
}
__device__ __forceinline__ void ffma2(u64 &acc, u64 w, u64 s) {
    asm("fma.rn.f32x2 %0, %1, %2, %0;" : "+l"(acc) : "l"(w), "l"(s));
}
__device__ __forceinline__ void fadd2(u64 &acc, u64 a) {
    asm("add.rn.f32x2 %0, %1, %0;" : "+l"(acc) : "l"(a));
}
__device__ __forceinline__ void pfma4(u64 (&A)[2], u64 s2, const float* w) {
    ulonglong2 w0 = ldu2(w);
    ffma2(A[0], w0.x, s2); ffma2(A[1], w0.y, s2);
}
__device__ __forceinline__ void pbias4(u64 (&A)[2], const float* p) {
    ulonglong2 b0 = ldu2(p);
    A[0] = b0.x; A[1] = b0.y;
}
__device__ __forceinline__ void unp4(const u64 (&A)[2], float (&o)[4]) {
    up2(A[0], o[0], o[1]); up2(A[1], o[2], o[3]);
}
__device__ __forceinline__ void load16(float (&r)[16], const float* p) {
    float4 v0 = ld4(p), v1 = ld4(p+4), v2 = ld4(p+8), v3 = ld4(p+12);
    r[0]=v0.x; r[1]=v0.y; r[2]=v0.z; r[3]=v0.w;
    r[4]=v1.x; r[5]=v1.y; r[6]=v1.z; r[7]=v1.w;
    r[8]=v2.x; r[9]=v2.y; r[10]=v2.z; r[11]=v2.w;
    r[12]=v3.x; r[13]=v3.y; r[14]=v3.z; r[15]=v3.w;
}
__device__ __forceinline__ void st4f(float* p, const float (&a)[4]) {
    *reinterpret_cast<float4*>(p) = make_float4(a[0], a[1], a[2], a[3]);
}
__device__ __forceinline__ void stu1(float* p, const u64 (&A)[2]) {
    ulonglong2 v; v.x = A[0]; v.y = A[1];
    *reinterpret_cast<ulonglong2*>(p) = v;
}
// one scalar-group (4 rows) of a 16-row x 4-edge GEMV, quad col slice.
// Wrow = base of row group (col-sliced); sk = a_full[rowgrp..rowgrp+3] of edge k.
__device__ __forceinline__ void grp4(u64 (&M0)[2], u64 (&M1)[2],
                                     u64 (&M2)[2], u64 (&M3)[2],
                                     float4 s0, float4 s1, float4 s2, float4 s3,
                                     const float* Wrow) {
    u64 b;
    {   ulonglong2 w = ldu2(Wrow);
        b = bc2(s0.x); ffma2(M0[0], w.x, b); ffma2(M0[1], w.y, b);
        b = bc2(s1.x); ffma2(M1[0], w.x, b); ffma2(M1[1], w.y, b);
        b = bc2(s2.x); ffma2(M2[0], w.x, b); ffma2(M2[1], w.y, b);
        b = bc2(s3.x); ffma2(M3[0], w.x, b); ffma2(M3[1], w.y, b);
    }
    {   ulonglong2 w = ldu2(Wrow + 16);
        b = bc2(s0.y); ffma2(M0[0], w.x, b); ffma2(M0[1], w.y, b);
        b = bc2(s1.y); ffma2(M1[0], w.x, b); ffma2(M1[1], w.y, b);
        b = bc2(s2.y); ffma2(M2[0], w.x, b); ffma2(M2[1], w.y, b);
        b = bc2(s3.y); ffma2(M3[0], w.x, b); ffma2(M3[1], w.y, b);
    }
    {   ulonglong2 w = ldu2(Wrow + 32);
        b = bc2(s0.z); ffma2(M0[0], w.x, b); ffma2(M0[1], w.y, b);
        b = bc2(s1.z); ffma2(M1[0], w.x, b); ffma2(M1[1], w.y, b);
        b = bc2(s2.z); ffma2(M2[0], w.x, b); ffma2(M2[1], w.y, b);
        b = bc2(s3.z); ffma2(M3[0], w.x, b); ffma2(M3[1], w.y, b);
    }
    {   ulonglong2 w = ldu2(Wrow + 48);
        b = bc2(s0.w); ffma2(M0[0], w.x, b); ffma2(M0[1], w.y, b);
        b = bc2(s1.w); ffma2(M1[0], w.x, b); ffma2(M1[1], w.y, b);
        b = bc2(s2.w); ffma2(M2[0], w.x, b); ffma2(M2[1], w.y, b);
        b = bc2(s3.w); ffma2(M3[0], w.x, b); ffma2(M3[1], w.y, b);
    }
}
// full 16-row x 4-edge GEMV stage with inputs in s_st (per-edge 16-vectors)
__device__ __forceinline__ void gemv_ex(u64 (&M0)[2], u64 (&M1)[2],
                                        u64 (&M2)[2], u64 (&M3)[2],
                                        const float* st_row,   // &s_st[i][0]
                                        const float* Wb) {     // col-sliced base
    #pragma unroll
    for (int g = 0; g < 4; ++g) {
        float4 s0 = ld4(st_row +  0 + g * 4);
        float4 s1 = ld4(st_row + 16 + g * 4);
        float4 s2 = ld4(st_row + 32 + g * 4);
        float4 s3 = ld4(st_row + 48 + g * 4);
        grp4(M0, M1, M2, M3, s0, s1, s2, s3, Wb + (g * 4) * 16);
    }
}

__global__ void __launch_bounds__(4 * N_, 2)
egnn_kernel(const float* __restrict__ data,      // [B, N, 3+N]
            const float* __restrict__ emb_w,     // [N, H]
            const float* __restrict__ ein_w, const float* __restrict__ ein_b,
            const float* __restrict__ eout_w, const float* __restrict__ eout_b,
            const float* __restrict__ fc_w,  const float* __restrict__ fc_b,
            const float* __restrict__ e1_w,  const float* __restrict__ e1_b,
            const float* __restrict__ e2_w,  const float* __restrict__ e2_b,
            const float* __restrict__ n1_w,  const float* __restrict__ n1_b,
            const float* __restrict__ n2_w,  const float* __restrict__ n2_b,
            const float* __restrict__ c1_w,  const float* __restrict__ c1_b,
            const float* __restrict__ c2_w,
            float* __restrict__ out)             // [B, NC]
{
    const int b   = blockIdx.x;
    const int tid = threadIdx.x;
    const int i   = tid >> 2;        // node 0..127
    const int q   = tid & 3;         // lane within quad
    const int q4  = q * 4;           // owned output-column slice base

    __shared__ __align__(16) float s_h[N_][HS];
    __shared__ __align__(16) float s_y[N_][HS];
    __shared__ __align__(16) float s_st[N_][ES];    // per-node exchange row
    __shared__ __align__(16) float4 s_x4[N_];
    __shared__ __align__(16) float s_part[32][17];

    __shared__ __align__(16) float w_e1[NL_ * SZ_E1], w_e2[NL_ * SZ_E2];
    __shared__ __align__(16) float w_n1[NL_ * SZ_N1], w_n2[NL_ * SZ_N2];
    __shared__ __align__(16) float w_c1[NL_ * SZ_C1], w_c2[NL_ * SZ_C2];
    __shared__ __align__(16) float b_e1[NL_ * 16], b_e2[NL_ * 16];
    __shared__ __align__(16) float b_n1[NL_ * 16], b_n2[NL_ * 16], b_c1[NL_ * 16];
    __shared__ __align__(16) float s_ein[16 * 16], sb_ein[16];
    __shared__ __align__(16) float s_eout[16 * 16], sb_eout[16];
    __shared__ float s_fc[16 * NC_], sb_fc[NC_];
    __shared__ float s_pool[H_];

    const int NT = 4 * N_;
    for (int t = tid; t < NL_ * SZ_E1; t += NT) w_e1[t] = e1_w[t];
    for (int t = tid; t < NL_ * SZ_E2; t += NT) w_e2[t] = e2_w[t];
    for (int t = tid; t < NL_ * SZ_N1; t += NT) w_n1[t] = n1_w[t];
    for (int t = tid; t < NL_ * SZ_N2; t += NT) w_n2[t] = n2_w[t];
    for (int t = tid; t < NL_ * SZ_C1; t += NT) w_c1[t] = c1_w[t];
    for (int t = tid; t < NL_ * SZ_C2; t += NT) w_c2[t] = c2_w[t];
    for (int t = tid; t < NL_ * 16; t += NT) {
        b_e1[t] = e1_b[t]; b_e2[t] = e2_b[t];
        b_n1[t] = n1_b[t]; b_n2[t] = n2_b[t]; b_c1[t] = c1_b[t];
    }
    for (int t = tid; t < 16 * 16; t += NT) { s_ein[t] = ein_w[t]; s_eout[t] = eout_w[t]; }
    if (tid < 16) { sb_ein[tid] = ein_b[tid]; sb_eout[tid] = eout_b[tid]; }
    for (int t = tid; t < 16 * NC_; t += NT) s_fc[t] = fc_w[t];
    if (tid < NC_) sb_fc[tid] = fc_b[tid];

    float xi0, xi1, xi2;
    {
        const float* dptr = data + ((size_t)b * N_ + i) * (3 + N_);
        xi0 = dptr[0]; xi1 = dptr[1]; xi2 = dptr[2];
    }
    __syncthreads();

    // ---- init: h = emb @ ein_w + ein_b (quad 4x4 split) ----
    {
        u64 acc[2];
        pbias4(acc, sb_ein + q4);
        const float* er = emb_w + i * H_;
        #pragma unroll
        for (int k = 0; k < 16; ++k) pfma4(acc, bc2(er[k]), s_ein + k * 16 + q4);
        stu1(&s_h[i][q4], acc);
        if (q == 0) s_x4[i] = make_float4(xi0, xi1, xi2, 0.0f);
    }
    __syncthreads();

    // ---- E_GCL layers ----
    #pragma unroll 1
    for (int l = 0; l < NL_; ++l) {
        const float* We1q = w_e1 + l * SZ_E1 + q4;
        const float* E2q  = w_e2 + l * SZ_E2 + q4;
        const float* C1q  = w_c1 + l * SZ_C1 + q4;

        // Phase A: pre = bias + e_attr row + h_i @ rows0-15 (own 4 cols);
        //          y_i = h_i @ rows16-31 -> s_y
        u64 pre[2];
        {
            float hf[16]; load16(hf, &s_h[i][0]);
            pbias4(pre, b_e1 + l * 16 + q4);
            pfma4(pre, bc2(1.0f), We1q + 33 * 16);
            u64 yq[2] = {0, 0};
            #pragma unroll
            for (int k = 0; k < 16; ++k) {
                const u64 s2 = bc2(hf[k]);
                pfma4(pre, s2, We1q + k * 16);
                pfma4(yq,  s2, We1q + (16 + k) * 16);
            }
            stu1(&s_y[i][q4], yq);
        }
        __syncthreads();   // s_y + s_x visible block-wide

        float accm[4] = {0.f, 0.f, 0.f, 0.f};
        float ax0 = 0.f, ax1 = 0.f, ax2 = 0.f;   // partial-t accumulators

        #pragma unroll 1
        for (int it = 0; it < 4; ++it) {       // 4 edges per iteration
            const int d  = 1 + 4 * it;
            const int j0 = (i + d)     & (N_ - 1);
            const int j1 = (i + d + 1) & (N_ - 1);
            const int j2 = (i + d + 2) & (N_ - 1);
            const int j3 = (i + d + 3) & (N_ - 1);

            // e1: a_k = silu(pre + y_jk + rad_k * w32)   (own 4 cols)
            {
                const ulonglong2 w32 = ldu2(We1q + 32 * 16);
                float4 x0 = s_x4[j0], x1 = s_x4[j1], x2 = s_x4[j2], x3 = s_x4[j3];
                float dx, dy, dz;
                float a[4];
                // edge 0
                dx = xi0-x0.x; dy = xi1-x0.y; dz = xi2-x0.z;
                {
                    ulonglong2 y = ldu2(&s_y[j0][q4]);
                    u64 A[2] = {y.x, y.y};
                    fadd2(A[0], pre[0]); fadd2(A[1], pre[1]);
                    const u64 r2 = bc2(fmaf(dx,dx, fmaf(dy,dy, dz*dz)));
                    ffma2(A[0], w32.x, r2); ffma2(A[1], w32.y, r2);
                    unp4(A, a);
                    a[0]=silu_f(a[0]); a[1]=silu_f(a[1]);
                    a[2]=silu_f(a[2]); a[3]=silu_f(a[3]);
                    st4f(&s_st[i][0 + q4], a);
                }
                // edge 1
                dx = xi0-x1.x; dy = xi1-x1.y; dz = xi2-x1.z;
                {
                    ulonglong2 y = ldu2(&s_y[j1][q4]);
                    u64 A[2] = {y.x, y.y};
                    fadd2(A[0], pre[0]); fadd2(A[1], pre[1]);
                    const u64 r2 = bc2(fmaf(dx,dx, fmaf(dy,dy, dz*dz)));
                    ffma2(A[0], w32.x, r2); ffma2(A[1], w32.y, r2);
                    unp4(A, a);
                    a[0]=silu_f(a[0]); a[1]=silu_f(a[1]);
                    a[2]=silu_f(a[2]); a[3]=silu_f(a[3]);
                    st4f(&s_st[i][16 + q4], a);
                }
                // edge 2
                dx = xi0-x2.x; dy = xi1-x2.y; dz = xi2-x2.z;
                {
                    ulonglong2 y = ldu2(&s_y[j2][q4]);
                    u64 A[2] = {y.x, y.y};
                    fadd2(A[0], pre[0]); fadd2(A[1], pre[1]);
                    const u64 r2 = bc2(fmaf(dx,dx, fmaf(dy,dy, dz*dz)));
                    ffma2(A[0], w32.x, r2); ffma2(A[1], w32.y, r2);
                    unp4(A, a);
                    a[0]=silu_f(a[0]); a[1]=silu_f(a[1]);
                    a[2]=silu_f(a[2]); a[3]=silu_f(a[3]);
                    st4f(&s_st[i][32 + q4], a);
                }
                // edge 3
                dx = xi0-x3.x; dy = xi1-x3.y; dz = xi2-x3.z;
                {
                    ulonglong2 y = ldu2(&s_y[j3][q4]);
                    u64 A[2] = {y.x, y.y};
                    fadd2(A[0], pre[0]); fadd2(A[1], pre[1]);
                    const u64 r2 = bc2(fmaf(dx,dx, fmaf(dy,dy, dz*dz)));
                    ffma2(A[0], w32.x, r2); ffma2(A[1], w32.y, r2);
                    unp4(A, a);
                    a[0]=silu_f(a[0]); a[1]=silu_f(a[1]);
                    a[2]=silu_f(a[2]); a[3]=silu_f(a[3]);
                    st4f(&s_st[i][48 + q4], a);
                }
            }
            __syncwarp();

            // e2: m_k = silu(a_full @ We2 + b); inputs from s_st
            float m0[4], m1[4], m2[4], m3[4];
            {
                u64 M0[2], M1[2], M2[2], M3[2];
                pbias4(M0, b_e2 + l * 16 + q4);
                M1[0]=M0[0]; M1[1]=M0[1];
                M2[0]=M0[0]; M2[1]=M0[1];
                M3[0]=M0[0]; M3[1]=M0[1];
                gemv_ex(M0, M1, M2, M3, &s_st[i][0], E2q);
                unp4(M0, m0); unp4(M1, m1); unp4(M2, m2); unp4(M3, m3);
            }
            #pragma unroll
            for (int o = 0; o < 4; ++o) {
                m0[o] = silu_f(m0[o]); m1[o] = silu_f(m1[o]);
                m2[o] = silu_f(m2[o]); m3[o] = silu_f(m3[o]);
                accm[o] += (m0[o] + m1[o]) + (m2[o] + m3[o]);
            }
            __syncwarp();   // a-reads complete before overwrite
            st4f(&s_st[i][0  + q4], m0);
            st4f(&s_st[i][16 + q4], m1);
            st4f(&s_st[i][32 + q4], m2);
            st4f(&s_st[i][48 + q4], m3);
            __syncwarp();

            // c1: silu(m_full @ Wc1 + b), then t_k = . Wc2 (own-4 partial)
            float t0, t1, t2, t3;
            {
                u64 T0[2], T1[2], T2[2], T3[2];
                pbias4(T0, b_c1 + l * 16 + q4);
                T1[0]=T0[0]; T1[1]=T0[1];
                T2[0]=T0[0]; T2[1]=T0[1];
                T3[0]=T0[0]; T3[1]=T0[1];
                gemv_ex(T0, T1, T2, T3, &s_st[i][0], C1q);
                float c0[4], c1v[4], c2v[4], c3[4];
                unp4(T0, c0); unp4(T1, c1v); unp4(T2, c2v); unp4(T3, c3);
                float4 w = ld4(w_c2 + l * SZ_C2 + q4);
                t0 = silu_f(c0[0]) * w.x;
                t0 = fmaf(silu_f(c0[1]), w.y, t0);
                t0 = fmaf(silu_f(c0[2]), w.z, t0);
                t0 = fmaf(silu_f(c0[3]), w.w, t0);
                t1 = silu_f(c1v[0]) * w.x;
                t1 = fmaf(silu_f(c1v[1]), w.y, t1);
                t1 = fmaf(silu_f(c1v[2]), w.z, t1);
                t1 = fmaf(silu_f(c1v[3]), w.w, t1);
                t2 = silu_f(c2v[0]) * w.x;
                t2 = fmaf(silu_f(c2v[1]), w.y, t2);
                t2 = fmaf(silu_f(c2v[2]), w.z, t2);
                t2 = fmaf(silu_f(c2v[3]), w.w, t2);
                t3 = silu_f(c3[0]) * w.x;
                t3 = fmaf(silu_f(c3[1]), w.y, t3);
                t3 = fmaf(silu_f(c3[2]), w.z, t3);
                t3 = fmaf(silu_f(c3[3]), w.w, t3);
            }

            // coord contributions with partial t (diffs recomputed)
            {
                float4 x0 = s_x4[j0], x1 = s_x4[j1], x2 = s_x4[j2], x3 = s_x4[j3];
                ax0 = fmaf(xi0-x0.x, t0, fmaf(xi0-x1.x, t1,
                      fmaf(xi0-x2.x, t2, fmaf(xi0-x3.x, t3, ax0))));
                ax1 = fmaf(xi1-x0.y, t0, fmaf(xi1-x1.y, t1,
                      fmaf(xi1-x2.y, t2, fmaf(xi1-x3.y, t3, ax1))));
                ax2 = fmaf(xi2-x0.z, t0, fmaf(xi2-x1.z, t1,
                      fmaf(xi2-x2.z, t2, fmaf(xi2-x3.z, t3, ax2))));
            }
            __syncwarp();   // m-reads complete before next iter's a stores
        }

        // quad-reduce partial coord accumulators once per layer
        ax0 += __shfl_xor_sync(FULL, ax0, 1, 4);
        ax0 += __shfl_xor_sync(FULL, ax0, 2, 4);
        ax1 += __shfl_xor_sync(FULL, ax1, 1, 4);
        ax1 += __shfl_xor_sync(FULL, ax1, 2, 4);
        ax2 += __shfl_xor_sync(FULL, ax2, 1, 4);
        ax2 += __shfl_xor_sync(FULL, ax2, 2, 4);
        xi0 = fmaf(ax0, 0.0625f, xi0);   // cnt == 16
        xi1 = fmaf(ax1, 0.0625f, xi1);
        xi2 = fmaf(ax2, 0.0625f, xi2);

        __syncthreads();   // all Phase-B reads of s_y / s_x done block-wide

        // Phase C: node_mlp (quad 4x4 split); exchange via s_st
        {
            const float* Wn1q = w_n1 + l * SZ_N1 + q4;
            const float* Wn2q = w_n2 + l * SZ_N2 + q4;

            st4f(&s_st[i][q4], accm);
            __syncwarp();
            float hf[16]; load16(hf, &s_h[i][0]);
            float af[16]; load16(af, &s_st[i][0]);

            float na[4];
            {
                u64 NA[2];
                pbias4(NA, b_n1 + l * 16 + q4);
                #pragma unroll
                for (int k = 0; k < 16; ++k) {
                    pfma4(NA, bc2(hf[k]), Wn1q + k * 16);
                    pfma4(NA, bc2(af[k]), Wn1q + (16 + k) * 16);
                }
                unp4(NA, na);
            }
            #pragma unroll
            for (int o = 0; o < 4; ++o) na[o] = silu_f(na[o]);

            __syncwarp();
            st4f(&s_st[i][q4], na);
            __syncwarp();
            float nf[16]; load16(nf, &s_st[i][0]);

            float hb[4];
            {
                u64 HB[2];
                pbias4(HB, b_n2 + l * 16 + q4);
                #pragma unroll
                for (int k = 0; k < 16; ++k) pfma4(HB, bc2(nf[k]), Wn2q + k * 16);
                unp4(HB, hb);
            }
            hb[0] += hf[q4 + 0]; hb[1] += hf[q4 + 1];   // residual: note hf is
            hb[2] += hf[q4 + 2]; hb[3] += hf[q4 + 3];   // indexed by constants
            __syncwarp();
            st4f(&s_h[i][q4], hb);
            if (q == 0) s_x4[i] = make_float4(xi0, xi1, xi2, 0.0f);
        }
        __syncwarp();
    }

    // ---- embedding_out + pooling ----
    {
        float hf[16]; load16(hf, &s_h[i][0]);
        u64 HO[2];
        pbias4(HO, sb_eout + q4);
        #pragma unroll
        for (int k = 0; k < 16; ++k) pfma4(HO, bc2(hf[k]), s_eout + k * 16 + q4);
        __syncwarp();
        stu1(&s_h[i][q4], HO);
    }
    __syncthreads();

    {
        const int col = tid & 15;
        const int chunk = tid >> 4;   // 0..31
        const int r0 = chunk * 4;
        float s = 0.0f;
        #pragma unroll
        for (int r = 0; r < 4; ++r) s += s_h[r0 + r][col];
        s_part[chunk][col] = s;
    }
    __syncthreads();
    if (tid < H_) {
        float s = 0.0f;
        #pragma unroll
        for (int c = 0; c < 32; ++c) s += s_part[c][tid];
        s_pool[tid] = s * (1.0f / (float)N_);
    }
    __syncthreads();

    if (tid == 0) {
        float logit[NC_];
        float mx = -1e30f;
        #pragma unroll
        for (int c = 0; c < NC_; ++c) {
            float s = sb_fc[c];
            #pragma unroll
            for (int k = 0; k < H_; ++k) s = fmaf(s_pool[k], s_fc[k * NC_ + c], s);
            logit[c] = s;
            mx = fmaxf(mx, s);
        }
        float den = 0.0f;
        float ev[NC_];
        #pragma unroll
        for (int c = 0; c < NC_; ++c) { ev[c] = expf(logit[c] - mx); den += ev[c]; }
        const float inv = 1.0f / den;
        #pragma unroll
        for (int c = 0; c < NC_; ++c) out[b * NC_ + c] = ev[c] * inv;
    }
}

extern "C" void kernel_launch(void* const* d_in, const int* in_sizes, int n_in,
                              void* d_out, int out_size)
{
    const float* data   = (const float*)d_in[0];
    const float* emb_w  = (const float*)d_in[3];
    const float* ein_w  = (const float*)d_in[4];
    const float* ein_b  = (const float*)d_in[5];
    const float* eout_w = (const float*)d_in[6];
    const float* eout_b = (const float*)d_in[7];
    const float* fc_w   = (const float*)d_in[8];
    const float* fc_b   = (const float*)d_in[9];
    const float* e1_w   = (const float*)d_in[10];
    const float* e1_b   = (const float*)d_in[11];
    const float* e2_w   = (const float*)d_in[12];
    const float* e2_b   = (const float*)d_in[13];
    const float* n1_w   = (const float*)d_in[14];
    const float* n1_b   = (const float*)d_in[15];
    const float* n2_w   = (const float*)d_in[16];
    const float* n2_b   = (const float*)d_in[17];
    const float* c1_w   = (const float*)d_in[18];
    const float* c1_b   = (const float*)d_in[19];
    const float* c2_w   = (const float*)d_in[20];
    float* out = (float*)d_out;

    egnn_kernel<<<B_, 4 * N_>>>(data, emb_w, ein_w, ein_b, eout_w, eout_b,
                                fc_w, fc_b, e1_w, e1_b, e2_w, e2_b,
                                n1_w, n1_b, n2_w, n2_b, c1_w, c1_b, c2_w, out);
}